// round 12
// baseline (speedup 1.0000x reference)
#include <cuda_runtime.h>
#include <cuda_bf16.h>
#include <cstdint>

// Complex attention, mma.sync bf16 3-term split. B=8 H=8 S=1024 D=64.
// R12: offline split+pre-swizzle kernel; GEMM fills become cp.async copies.
// K0: split Q(:=q/8),K,V fp32 -> bf16 hi/lo, SW128-pre-swizzled scratch
// K1: attn=(q/8).k -> spill + per-(row,ktile) mag^2 min/max  [128q x 64k]
// K2: row min/max reduce
// K3: normalize(attn) @ v                                    [128q x 64d]

#define NKT 16
typedef unsigned long long u64;
typedef uint32_t u32;

// attn spill
__device__ float g_ar[(size_t)64 * 1024 * 1024];   // 256 MB
__device__ float g_ai[(size_t)64 * 1024 * 1024];   // 256 MB
__device__ float g_pmin[64 * 1024 * NKT];
__device__ float g_pmax[64 * 1024 * NKT];
__device__ float g_mn[64 * 1024];
__device__ float g_inv[64 * 1024];
// pre-split operands: [4] = {re_hi, re_lo, im_hi, im_lo}, each [64][1024][64] bf16
__device__ __align__(16) __nv_bfloat16 g_sq[4][(size_t)64 * 1024 * 64];
__device__ __align__(16) __nv_bfloat16 g_sk[4][(size_t)64 * 1024 * 64];
__device__ __align__(16) __nv_bfloat16 g_sv[4][(size_t)64 * 1024 * 64];

__device__ __forceinline__ u32 smem_u32(const void* p) {
    u32 a;
    asm("{ .reg .u64 t; cvta.to.shared.u64 t, %1; cvt.u32.u64 %0, t; }"
        : "=r"(a) : "l"(p));
    return a;
}

#define SW128(x) ((x) ^ (((x) >> 3) & 0x70))
#define NEGS 0x80008000u
#define TB16 16384
#define TB8  8192

#define CPASYNC(smoff, gptr) \
    asm volatile("cp.async.cg.shared.global [%0], [%1], 16;" :: "r"(smoff), "l"(gptr) : "memory")
#define CPCOMMIT() asm volatile("cp.async.commit_group;" ::: "memory")
#define CPWAIT0()  asm volatile("cp.async.wait_group 0;" ::: "memory")

__device__ __forceinline__ void ldmx4(u32* r, u32 a) {
    asm volatile("ldmatrix.sync.aligned.m8n8.x4.shared.b16 {%0,%1,%2,%3}, [%4];"
        : "=r"(r[0]), "=r"(r[1]), "=r"(r[2]), "=r"(r[3]) : "r"(a));
}
__device__ __forceinline__ void ldmx2(u32* r, u32 a) {
    asm volatile("ldmatrix.sync.aligned.m8n8.x2.shared.b16 {%0,%1}, [%2];"
        : "=r"(r[0]), "=r"(r[1]) : "r"(a));
}
__device__ __forceinline__ void ldmx2t(u32* r, u32 a) {
    asm volatile("ldmatrix.sync.aligned.m8n8.x2.trans.shared.b16 {%0,%1}, [%2];"
        : "=r"(r[0]), "=r"(r[1]) : "r"(a));
}
__device__ __forceinline__ void mma16816(float* c, const u32* a, const u32* b) {
    asm volatile("mma.sync.aligned.m16n8k16.row.col.f32.bf16.bf16.f32 "
        "{%0,%1,%2,%3}, {%4,%5,%6,%7}, {%8,%9}, {%0,%1,%2,%3};"
        : "+f"(c[0]), "+f"(c[1]), "+f"(c[2]), "+f"(c[3])
        : "r"(a[0]), "r"(a[1]), "r"(a[2]), "r"(a[3]), "r"(b[0]), "r"(b[1]));
}

__device__ __forceinline__ void split_pair(float2 v, u32& h_, u32& l_) {
    __nv_bfloat162 h = __float22bfloat162_rn(v);
    float2 hf = __bfloat1622float2(h);
    __nv_bfloat162 l = __float22bfloat162_rn(make_float2(v.x - hf.x, v.y - hf.y));
    h_ = *(u32*)&h; l_ = *(u32*)&l;
}
// smem split-store, SW128 layout (128B rows)
__device__ __forceinline__ void st_split2(char* hi, char* lo, int row, int cp, float2 v) {
    u32 h, l; split_pair(v, h, l);
    u32 off = SW128((u32)(row * 128 + cp * 4));
    *(u32*)(hi + off) = h;
    *(u32*)(lo + off) = l;
}

// ---------------------------------------------------------------------------
// K0: split + pre-swizzle. One thread per (bh,row,colpair): handles q,k,v r+i.
// ---------------------------------------------------------------------------
__global__ void split_kernel(
    const float* __restrict__ qr, const float* __restrict__ qi,
    const float* __restrict__ kr, const float* __restrict__ ki,
    const float* __restrict__ vr, const float* __restrict__ vi)
{
    int t = blockIdx.x * 256 + threadIdx.x;        // 2,097,152 threads
    int bh = t >> 15, rem = t & 32767;
    int row = rem >> 5, cp = rem & 31;
    size_t gi = ((((size_t)bh << 10) + row) << 6) + cp * 2;
    size_t boff = ((size_t)bh << 17) + SW128((u32)(row * 128 + cp * 4));

    u32 h, l;
    float2 a = *(const float2*)(qr + gi);
    a.x *= 0.125f; a.y *= 0.125f;
    split_pair(a, h, l);
    *(u32*)((char*)g_sq[0] + boff) = h; *(u32*)((char*)g_sq[1] + boff) = l;
    float2 b = *(const float2*)(qi + gi);
    b.x *= 0.125f; b.y *= 0.125f;
    split_pair(b, h, l);
    *(u32*)((char*)g_sq[2] + boff) = h; *(u32*)((char*)g_sq[3] + boff) = l;

    split_pair(*(const float2*)(kr + gi), h, l);
    *(u32*)((char*)g_sk[0] + boff) = h; *(u32*)((char*)g_sk[1] + boff) = l;
    split_pair(*(const float2*)(ki + gi), h, l);
    *(u32*)((char*)g_sk[2] + boff) = h; *(u32*)((char*)g_sk[3] + boff) = l;

    split_pair(*(const float2*)(vr + gi), h, l);
    *(u32*)((char*)g_sv[0] + boff) = h; *(u32*)((char*)g_sv[1] + boff) = l;
    split_pair(*(const float2*)(vi + gi), h, l);
    *(u32*)((char*)g_sv[2] + boff) = h; *(u32*)((char*)g_sv[3] + boff) = l;
}

// ---------------------------------------------------------------------------
// K1: QK. CTA tile 128q x 64k, 8 warps (4m x 2n), warp tile 32q x 32k.
// Fills via cp.async from pre-split scratch. 2 CTAs/SM.
// attn_r = qr.kr - qi.ki ; attn_i = qr.ki + qi.kr
// ---------------------------------------------------------------------------
__global__ __launch_bounds__(256, 2) void qk_kernel()
{
    extern __shared__ __align__(128) char sm[];
    char* s_q = sm;                 // 4 x 16KB
    char* s_k = sm + 4 * TB16;      // 4 x 8KB
    __shared__ float sMin[128][2], sMax[128][2];

    const int tid = threadIdx.x, wid = tid >> 5, lane = tid & 31;
    const int kt = blockIdx.x, qt = blockIdx.y, bh = blockIdx.z;

    // ---- fill via cp.async ----
    {
        const u32 usq = smem_u32(s_q), usk = smem_u32(s_k);
        const size_t qbyte = ((size_t)bh << 17) + ((size_t)qt << 14);
        const size_t kbyte = ((size_t)bh << 17) + ((size_t)kt << 13);
        #pragma unroll
        for (int arr = 0; arr < 4; ++arr) {
            #pragma unroll
            for (int it = 0; it < 4; ++it) {
                u32 off = tid * 16 + it * 4096;
                CPASYNC(usq + arr * TB16 + off, (const char*)g_sq[arr] + qbyte + off);
            }
            #pragma unroll
            for (int it = 0; it < 2; ++it) {
                u32 off = tid * 16 + it * 4096;
                CPASYNC(usk + arr * TB8 + off, (const char*)g_sk[arr] + kbyte + off);
            }
        }
        CPCOMMIT();
        CPWAIT0();
    }
    __syncthreads();

    // ---- compute (R7 verbatim) ----
    const int wm = wid >> 1, wn = wid & 1;
    const int g = lane >> 2, tg = lane & 3;
    float accR[2][4][4] = {}, accI[2][4][4] = {};

    const u32 uq0 = smem_u32(s_q), uq1 = uq0 + TB16;
    const u32 uq2 = uq0 + 2 * TB16, uq3 = uq0 + 3 * TB16;
    const u32 uk0 = smem_u32(s_k), uk1 = uk0 + TB8;
    const u32 uk2 = uk0 + 2 * TB8, uk3 = uk0 + 3 * TB8;

    const u32 a_row = (u32)(wm * 32 + (lane & 15));
    const u32 a_cb  = (u32)((lane >> 4) * 16);
    const u32 b_row = (u32)(wn * 32 + (lane & 7));
    const u32 b_cb  = (u32)(((lane >> 3) & 1) * 16);

    #pragma unroll
    for (int kb = 0; kb < 4; ++kb) {
        u32 Aqrh[2][4], Aqrl[2][4], Aqih[2][4], Aqil[2][4];
        #pragma unroll
        for (int mb = 0; mb < 2; ++mb) {
            u32 off = SW128((a_row + mb * 16) * 128 + kb * 32 + a_cb);
            ldmx4(Aqrh[mb], uq0 + off);
            ldmx4(Aqrl[mb], uq1 + off);
            ldmx4(Aqih[mb], uq2 + off);
            ldmx4(Aqil[mb], uq3 + off);
        }
        #pragma unroll
        for (int nb = 0; nb < 4; ++nb) {
            u32 off = SW128((b_row + nb * 8) * 128 + kb * 32 + b_cb);
            u32 Bkrh[2], Bkrl[2], Bkih[2], Bkil[2];
            ldmx2(Bkrh, uk0 + off);
            ldmx2(Bkrl, uk1 + off);
            ldmx2(Bkih, uk2 + off);
            ldmx2(Bkil, uk3 + off);
            u32 Bknh[2] = { Bkih[0] ^ NEGS, Bkih[1] ^ NEGS };
            u32 Bknl[2] = { Bkil[0] ^ NEGS, Bkil[1] ^ NEGS };
            #pragma unroll
            for (int mb = 0; mb < 2; ++mb) {
                mma16816(accR[mb][nb], Aqrh[mb], Bkrh);
                mma16816(accR[mb][nb], Aqrh[mb], Bkrl);
                mma16816(accR[mb][nb], Aqrl[mb], Bkrh);
                mma16816(accR[mb][nb], Aqih[mb], Bknh);
                mma16816(accR[mb][nb], Aqih[mb], Bknl);
                mma16816(accR[mb][nb], Aqil[mb], Bknh);
                mma16816(accI[mb][nb], Aqrh[mb], Bkih);
                mma16816(accI[mb][nb], Aqrh[mb], Bkil);
                mma16816(accI[mb][nb], Aqrl[mb], Bkih);
                mma16816(accI[mb][nb], Aqih[mb], Bkrh);
                mma16816(accI[mb][nb], Aqih[mb], Bkrl);
                mma16816(accI[mb][nb], Aqil[mb], Bkrh);
            }
        }
    }

    // ---- epilogue: store attn + row mag^2 min/max ----
    #pragma unroll
    for (int mb = 0; mb < 2; ++mb)
        #pragma unroll
        for (int half = 0; half < 2; ++half) {
            int rl = wm * 32 + mb * 16 + half * 8 + g;
            size_t ab = (((size_t)((bh << 10) + (qt << 7) + rl)) << 10)
                      + (kt << 6) + wn * 32 + tg * 2;
            float mn = 3.4e38f, mx = 0.0f;
            #pragma unroll
            for (int nb = 0; nb < 4; ++nb) {
                float x0 = accR[mb][nb][half * 2], x1 = accR[mb][nb][half * 2 + 1];
                float y0 = accI[mb][nb][half * 2], y1 = accI[mb][nb][half * 2 + 1];
                *(float2*)(g_ar + ab + nb * 8) = make_float2(x0, x1);
                *(float2*)(g_ai + ab + nb * 8) = make_float2(y0, y1);
                float m0 = x0 * x0 + y0 * y0, m1 = x1 * x1 + y1 * y1;
                mn = fminf(mn, fminf(m0, m1));
                mx = fmaxf(mx, fmaxf(m0, m1));
            }
            mn = fminf(mn, __shfl_xor_sync(0xffffffffu, mn, 1));
            mn = fminf(mn, __shfl_xor_sync(0xffffffffu, mn, 2));
            mx = fmaxf(mx, __shfl_xor_sync(0xffffffffu, mx, 1));
            mx = fmaxf(mx, __shfl_xor_sync(0xffffffffu, mx, 2));
            if (tg == 0) { sMin[rl][wn] = mn; sMax[rl][wn] = mx; }
        }
    __syncthreads();
    if (tid < 128) {
        float mn = fminf(sMin[tid][0], sMin[tid][1]);
        float mx = fmaxf(sMax[tid][0], sMax[tid][1]);
        int row = (qt << 7) + tid;
        g_pmin[((bh << 10) + row) * NKT + kt] = mn;
        g_pmax[((bh << 10) + row) * NKT + kt] = mx;
    }
}

// ---------------------------------------------------------------------------
// K2: reduce 16 partials/row -> mn = sqrt(min m2), inv = 1/(mx - mn).
// ---------------------------------------------------------------------------
__global__ void minmax_kernel()
{
    int r = blockIdx.x * 256 + threadIdx.x;   // 65536 rows
    float mn2 = g_pmin[r * NKT], mx2 = g_pmax[r * NKT];
    #pragma unroll
    for (int t = 1; t < NKT; t++) {
        mn2 = fminf(mn2, g_pmin[r * NKT + t]);
        mx2 = fmaxf(mx2, g_pmax[r * NKT + t]);
    }
    float mnv = sqrtf(mn2), mxv = sqrtf(mx2);
    g_mn[r] = mnv;
    g_inv[r] = 1.0f / (mxv - mnv);
}

// ---------------------------------------------------------------------------
// K3: AV. CTA tile 128q x 64d; 16 k-chunks of 64. 8 warps (4m x 2n),
// warp tile 32q x 32d. A normalized+split in-kernel; V via cp.async.
// out_r = ar.vr - ai.vi ; out_i = ar.vi + ai.vr
// ---------------------------------------------------------------------------
__global__ __launch_bounds__(256, 2) void av_kernel(float* __restrict__ out)
{
    extern __shared__ __align__(128) char sm[];
    char* s_a = sm;                 // 4 x 16KB: arh, arl, aih, ail [128q][64k]
    char* s_v = sm + 4 * TB16;      // 4 x 8KB:  vrh, vrl, vih, vil [64k][64d]
    __shared__ float smn[128], sinv[128];

    const int tid = threadIdx.x, wid = tid >> 5, lane = tid & 31;
    const int qt = blockIdx.x, bh = blockIdx.y;
    const int cp = tid & 31, r0 = tid >> 5;

    if (tid < 128) {
        int r = (bh << 10) + (qt << 7) + tid;
        float mnv = g_mn[r], invv = g_inv[r];
        sinv[tid] = invv;
        smn[tid] = mnv * invv;   // pre-multiplied
    }
    __syncthreads();

    const int wm = wid >> 1, wn = wid & 1;
    const int g = lane >> 2, tg = lane & 3;
    float accR[2][4][4] = {}, accI[2][4][4] = {};

    const u32 ua0 = smem_u32(s_a), ua1 = ua0 + TB16;
    const u32 ua2 = ua0 + 2 * TB16, ua3 = ua0 + 3 * TB16;
    const u32 uv0 = smem_u32(s_v), uv1 = uv0 + TB8;
    const u32 uv2 = uv0 + 2 * TB8, uv3 = uv0 + 3 * TB8;

    const u32 a_row = (u32)(wm * 32 + (lane & 15));
    const u32 a_cb  = (u32)((lane >> 4) * 16);
    const u32 bt_row = (u32)(lane & 15);
    const u32 bt_cb  = (u32)(wn * 64);

    const size_t abase = ((size_t)((bh << 10) + (qt << 7))) << 10;

    for (int c = 0; c < 16; ++c) {
        // V fill via cp.async (issue first; lands during A fill)
        {
            const size_t vbyte = ((size_t)bh << 17) + ((size_t)c << 13);
            #pragma unroll
            for (int arr = 0; arr < 4; ++arr)
                #pragma unroll
                for (int it = 0; it < 2; ++it) {
                    u32 off = tid * 16 + it * 4096;
                    CPASYNC(uv0 + arr * TB8 + off, (const char*)g_sv[arr] + vbyte + off);
                }
            CPCOMMIT();
        }
        // A fill: normalized attn [128q][64k]
        #pragma unroll
        for (int it = 0; it < 16; ++it) {
            int row = r0 + (it << 3);
            size_t ao = abase + ((size_t)row << 10) + (c << 6) + cp * 2;
            float2 a = *(const float2*)(g_ar + ao);
            float2 b = *(const float2*)(g_ai + ao);
            float invv = sinv[row], mni = smn[row];
            float f0 = invv - mni * rsqrtf(a.x * a.x + b.x * b.x);
            float f1 = invv - mni * rsqrtf(a.y * a.y + b.y * b.y);
            st_split2(s_a, s_a + TB16, row, cp, make_float2(a.x * f0, a.y * f1));
            st_split2(s_a + 2 * TB16, s_a + 3 * TB16, row, cp,
                      make_float2(b.x * f0, b.y * f1));
        }
        CPWAIT0();
        __syncthreads();

        #pragma unroll
        for (int kb = 0; kb < 4; ++kb) {
            u32 Aarh[2][4], Aarl[2][4], Aaih[2][4], Aail[2][4];
            #pragma unroll
            for (int mb = 0; mb < 2; ++mb) {
                u32 off = SW128((a_row + mb * 16) * 128 + kb * 32 + a_cb);
                ldmx4(Aarh[mb], ua0 + off);
                ldmx4(Aarl[mb], ua1 + off);
                ldmx4(Aaih[mb], ua2 + off);
                ldmx4(Aail[mb], ua3 + off);
            }
            #pragma unroll
            for (int nb = 0; nb < 4; ++nb) {
                u32 off = SW128((bt_row + kb * 16) * 128 + bt_cb + nb * 16);
                u32 Bvrh[2], Bvrl[2], Bvih[2], Bvil[2];
                ldmx2t(Bvrh, uv0 + off);
                ldmx2t(Bvrl, uv1 + off);
                ldmx2t(Bvih, uv2 + off);
                ldmx2t(Bvil, uv3 + off);
                u32 Bvnh[2] = { Bvih[0] ^ NEGS, Bvih[1] ^ NEGS };
                u32 Bvnl[2] = { Bvil[0] ^ NEGS, Bvil[1] ^ NEGS };
                #pragma unroll
                for (int mb = 0; mb < 2; ++mb) {
                    mma16816(accR[mb][nb], Aarh[mb], Bvrh);
                    mma16816(accR[mb][nb], Aarh[mb], Bvrl);
                    mma16816(accR[mb][nb], Aarl[mb], Bvrh);
                    mma16816(accR[mb][nb], Aaih[mb], Bvnh);
                    mma16816(accR[mb][nb], Aaih[mb], Bvnl);
                    mma16816(accR[mb][nb], Aail[mb], Bvnh);
                    mma16816(accI[mb][nb], Aarh[mb], Bvih);
                    mma16816(accI[mb][nb], Aarh[mb], Bvil);
                    mma16816(accI[mb][nb], Aarl[mb], Bvih);
                    mma16816(accI[mb][nb], Aaih[mb], Bvrh);
                    mma16816(accI[mb][nb], Aaih[mb], Bvrl);
                    mma16816(accI[mb][nb], Aail[mb], Bvrh);
                }
            }
        }
        __syncthreads();
    }

    // ---- epilogue: out[2][64][1024][64], imag at +4194304 ----
    #pragma unroll
    for (int mb = 0; mb < 2; ++mb)
        #pragma unroll
        for (int half = 0; half < 2; ++half) {
            int row = (qt << 7) + wm * 32 + mb * 16 + half * 8 + g;
            int d = wn * 32 + tg * 2;
            size_t ob = ((size_t)((bh << 10) + row) << 6) + d;
            #pragma unroll
            for (int nb = 0; nb < 4; ++nb) {
                *(float2*)(out + ob + nb * 8) =
                    make_float2(accR[mb][nb][half * 2], accR[mb][nb][half * 2 + 1]);
                *(float2*)(out + ob + nb * 8 + 4194304) =
                    make_float2(accI[mb][nb][half * 2], accI[mb][nb][half * 2 + 1]);
            }
        }
}

extern "C" void kernel_launch(void* const* d_in, const int* in_sizes, int n_in,
                              void* d_out, int out_size)
{
    (void)in_sizes; (void)n_in; (void)out_size;
    const float* qr = (const float*)d_in[0];
    const float* qi = (const float*)d_in[1];
    const float* kr = (const float*)d_in[2];
    const float* ki = (const float*)d_in[3];
    const float* vr = (const float*)d_in[4];
    const float* vi = (const float*)d_in[5];
    float* out = (float*)d_out;

    const int smem = 4 * TB16 + 4 * TB8;   // 98304
    cudaFuncSetAttribute(qk_kernel, cudaFuncAttributeMaxDynamicSharedMemorySize, smem);
    cudaFuncSetAttribute(av_kernel, cudaFuncAttributeMaxDynamicSharedMemorySize, smem);

    split_kernel<<<8192, 256>>>(qr, qi, kr, ki, vr, vi);
    qk_kernel<<<dim3(16, 8, 64), 256, smem>>>();
    minmax_kernel<<<256, 256>>>();
    av_kernel<<<dim3(8, 64), 256, smem>>>(out);
}

// round 13
// speedup vs baseline: 1.6329x; 1.6329x over previous
#include <cuda_runtime.h>
#include <cstdint>

// Complex attention, single-pass TF32 mma.m16n8k8. B=8 H=8 S=1024 D=64.
// K1: attn=(q/8).k -> spill + per-(row,ktile) mag^2 min/max  [128q x 64k]
// K2: row min/max reduce
// K3: normalize(attn) @ v                                    [128q x 64d]
// attn_r = qr.kr - qi.ki ; attn_i = qr.ki + qi.kr  (negation via sign-bit XOR)

#define NKT 16
typedef unsigned long long u64;
typedef uint32_t u32;

__device__ float g_ar[(size_t)64 * 1024 * 1024];   // 256 MB
__device__ float g_ai[(size_t)64 * 1024 * 1024];   // 256 MB
__device__ float g_pmin[64 * 1024 * NKT];
__device__ float g_pmax[64 * 1024 * NKT];
__device__ float g_mn[64 * 1024];
__device__ float g_inv[64 * 1024];

#define PAD 68            // u32 per row (64 data + 4 pad) -> conflict-free LDS
#define NEGF 0x80000000u
#define QWORDS (128 * PAD)   // 8704 u32 = 34816 B
#define KWORDS (64 * PAD)    // 4352 u32 = 17408 B

__device__ __forceinline__ u32 tf32c(float x) {
    u32 r; asm("cvt.rna.tf32.f32 %0, %1;" : "=r"(r) : "f"(x)); return r;
}
__device__ __forceinline__ u64 pk2(u32 lo, u32 hi) {
    return (u64)lo | ((u64)hi << 32);
}
__device__ __forceinline__ void mma_tf32(float* c, const u32* a, const u32* b) {
    asm volatile("mma.sync.aligned.m16n8k8.row.col.f32.tf32.tf32.f32 "
        "{%0,%1,%2,%3}, {%4,%5,%6,%7}, {%8,%9}, {%0,%1,%2,%3};"
        : "+f"(c[0]), "+f"(c[1]), "+f"(c[2]), "+f"(c[3])
        : "r"(a[0]), "r"(a[1]), "r"(a[2]), "r"(a[3]), "r"(b[0]), "r"(b[1]));
}

// A fragment (m16k8): a0(g,tg) a1(g+8,tg) a2(g,tg+4) a3(g+8,tg+4)
__device__ __forceinline__ void ldA(u32* a, const u32* base, int row, int col) {
    a[0] = base[row * PAD + col];
    a[1] = base[(row + 8) * PAD + col];
    a[2] = base[row * PAD + col + 4];
    a[3] = base[(row + 8) * PAD + col + 4];
}

// ---------------------------------------------------------------------------
// K1: QK. CTA tile 128q x 64k, 8 warps (4m x 2n), warp tile 32q x 32k.
// smem: Q (re,im) fp32->tf32 [128][PAD], K (re,im) [64][PAD]. 2 CTAs/SM.
// ---------------------------------------------------------------------------
__global__ __launch_bounds__(256, 2) void qk_kernel(
    const float* __restrict__ qr, const float* __restrict__ qi,
    const float* __restrict__ kr, const float* __restrict__ ki)
{
    extern __shared__ __align__(16) u32 sm[];
    u32* Qr = sm;                 // [128][PAD]
    u32* Qi = Qr + QWORDS;
    u32* Kr = Qi + QWORDS;        // [64][PAD]
    u32* Ki = Kr + KWORDS;
    __shared__ float sMin[128][2], sMax[128][2];

    const int tid = threadIdx.x, wid = tid >> 5, lane = tid & 31;
    const int kt = blockIdx.x, qt = blockIdx.y, bh = blockIdx.z;
    const int fr = tid >> 5, cp2 = (tid & 31) * 2;

    // ---- fill (coalesced LDG.64, cvt, STS.64) ----
    {
        const size_t qbase = ((size_t)((bh << 10) + (qt << 7))) << 6;
        const size_t kbase = ((size_t)((bh << 10) + (kt << 6))) << 6;
        #pragma unroll
        for (int it = 0; it < 16; ++it) {
            int row = fr + (it << 3);
            float2 a = *(const float2*)(qr + qbase + (row << 6) + cp2);
            float2 b = *(const float2*)(qi + qbase + (row << 6) + cp2);
            *(u64*)(Qr + row * PAD + cp2) = pk2(tf32c(a.x * 0.125f), tf32c(a.y * 0.125f));
            *(u64*)(Qi + row * PAD + cp2) = pk2(tf32c(b.x * 0.125f), tf32c(b.y * 0.125f));
        }
        #pragma unroll
        for (int it = 0; it < 8; ++it) {
            int row = fr + (it << 3);
            float2 c = *(const float2*)(kr + kbase + (row << 6) + cp2);
            float2 d = *(const float2*)(ki + kbase + (row << 6) + cp2);
            *(u64*)(Kr + row * PAD + cp2) = pk2(tf32c(c.x), tf32c(c.y));
            *(u64*)(Ki + row * PAD + cp2) = pk2(tf32c(d.x), tf32c(d.y));
        }
    }
    __syncthreads();

    // ---- compute ----
    const int wm = wid >> 1, wn = wid & 1;
    const int g = lane >> 2, tg = lane & 3;
    float accR[2][4][4] = {}, accI[2][4][4] = {};

    #pragma unroll
    for (int kb = 0; kb < 8; ++kb) {
        const int kc = kb * 8 + tg;
        u32 aqr[2][4], aqi[2][4];
        #pragma unroll
        for (int mb = 0; mb < 2; ++mb) {
            int row = wm * 32 + mb * 16 + g;
            ldA(aqr[mb], Qr, row, kc);
            ldA(aqi[mb], Qi, row, kc);
        }
        #pragma unroll
        for (int nb = 0; nb < 4; ++nb) {
            int n0 = wn * 32 + nb * 8 + g;
            u32 bkr[2], bki[2], bkn[2];
            bkr[0] = Kr[n0 * PAD + kc];     bkr[1] = Kr[n0 * PAD + kc + 4];
            bki[0] = Ki[n0 * PAD + kc];     bki[1] = Ki[n0 * PAD + kc + 4];
            bkn[0] = bki[0] ^ NEGF;         bkn[1] = bki[1] ^ NEGF;
            #pragma unroll
            for (int mb = 0; mb < 2; ++mb) {
                mma_tf32(accR[mb][nb], aqr[mb], bkr);
                mma_tf32(accR[mb][nb], aqi[mb], bkn);
                mma_tf32(accI[mb][nb], aqr[mb], bki);
                mma_tf32(accI[mb][nb], aqi[mb], bkr);
            }
        }
    }

    // ---- epilogue: store attn + row mag^2 min/max ----
    #pragma unroll
    for (int mb = 0; mb < 2; ++mb)
        #pragma unroll
        for (int half = 0; half < 2; ++half) {
            int rl = wm * 32 + mb * 16 + half * 8 + g;
            size_t ab = (((size_t)((bh << 10) + (qt << 7) + rl)) << 10)
                      + (kt << 6) + wn * 32 + tg * 2;
            float mn = 3.4e38f, mx = 0.0f;
            #pragma unroll
            for (int nb = 0; nb < 4; ++nb) {
                float x0 = accR[mb][nb][half * 2], x1 = accR[mb][nb][half * 2 + 1];
                float y0 = accI[mb][nb][half * 2], y1 = accI[mb][nb][half * 2 + 1];
                *(float2*)(g_ar + ab + nb * 8) = make_float2(x0, x1);
                *(float2*)(g_ai + ab + nb * 8) = make_float2(y0, y1);
                float m0 = x0 * x0 + y0 * y0, m1 = x1 * x1 + y1 * y1;
                mn = fminf(mn, fminf(m0, m1));
                mx = fmaxf(mx, fmaxf(m0, m1));
            }
            mn = fminf(mn, __shfl_xor_sync(0xffffffffu, mn, 1));
            mn = fminf(mn, __shfl_xor_sync(0xffffffffu, mn, 2));
            mx = fmaxf(mx, __shfl_xor_sync(0xffffffffu, mx, 1));
            mx = fmaxf(mx, __shfl_xor_sync(0xffffffffu, mx, 2));
            if (tg == 0) { sMin[rl][wn] = mn; sMax[rl][wn] = mx; }
        }
    __syncthreads();
    if (tid < 128) {
        float mn = fminf(sMin[tid][0], sMin[tid][1]);
        float mx = fmaxf(sMax[tid][0], sMax[tid][1]);
        int row = (qt << 7) + tid;
        g_pmin[((bh << 10) + row) * NKT + kt] = mn;
        g_pmax[((bh << 10) + row) * NKT + kt] = mx;
    }
}

// ---------------------------------------------------------------------------
// K2: reduce 16 partials/row -> mn = sqrt(min m2), inv = 1/(mx - mn).
// ---------------------------------------------------------------------------
__global__ void minmax_kernel()
{
    int r = blockIdx.x * 256 + threadIdx.x;   // 65536 rows
    float mn2 = g_pmin[r * NKT], mx2 = g_pmax[r * NKT];
    #pragma unroll
    for (int t = 1; t < NKT; t++) {
        mn2 = fminf(mn2, g_pmin[r * NKT + t]);
        mx2 = fmaxf(mx2, g_pmax[r * NKT + t]);
    }
    float mnv = sqrtf(mn2), mxv = sqrtf(mx2);
    g_mn[r] = mnv;
    g_inv[r] = 1.0f / (mxv - mnv);
}

// ---------------------------------------------------------------------------
// K3: AV. CTA tile 128q x 64d; 16 k-chunks of 64. 8 warps (4m x 2n),
// warp tile 32q x 32d. A = normalized attn [128q][PAD]; V natural [64k][PAD]
// (B fragment read directly from [k][d] layout; worst 2-way LDS conflict).
// out_r = ar.vr - ai.vi ; out_i = ar.vi + ai.vr
// ---------------------------------------------------------------------------
__global__ __launch_bounds__(256, 2) void av_kernel(
    const float* __restrict__ vr, const float* __restrict__ vi,
    float* __restrict__ out)
{
    extern __shared__ __align__(16) u32 sm[];
    u32* Ar = sm;                 // [128][PAD]
    u32* Ai = Ar + QWORDS;
    u32* Vr = Ai + QWORDS;        // [64][PAD]
    u32* Vi = Vr + KWORDS;
    __shared__ float smn[128], sinv[128];

    const int tid = threadIdx.x, wid = tid >> 5, lane = tid & 31;
    const int qt = blockIdx.x, bh = blockIdx.y;
    const int fr = tid >> 5, cp2 = (tid & 31) * 2;

    if (tid < 128) {
        int r = (bh << 10) + (qt << 7) + tid;
        float mnv = g_mn[r], invv = g_inv[r];
        sinv[tid] = invv;
        smn[tid] = mnv * invv;   // pre-multiplied
    }
    __syncthreads();

    const int wm = wid >> 1, wn = wid & 1;
    const int g = lane >> 2, tg = lane & 3;
    float accR[2][4][4] = {}, accI[2][4][4] = {};

    const size_t abase = ((size_t)((bh << 10) + (qt << 7))) << 10;
    const size_t vbase = ((size_t)(bh << 10)) << 6;

    for (int c = 0; c < 16; ++c) {
        // A fill: normalized attn [128q][64k] -> tf32
        #pragma unroll
        for (int it = 0; it < 16; ++it) {
            int row = fr + (it << 3);
            size_t ao = abase + ((size_t)row << 10) + (c << 6) + cp2;
            float2 a = *(const float2*)(g_ar + ao);
            float2 b = *(const float2*)(g_ai + ao);
            float invv = sinv[row], mni = smn[row];
            float f0 = invv - mni * rsqrtf(a.x * a.x + b.x * b.x);
            float f1 = invv - mni * rsqrtf(a.y * a.y + b.y * b.y);
            *(u64*)(Ar + row * PAD + cp2) = pk2(tf32c(a.x * f0), tf32c(a.y * f1));
            *(u64*)(Ai + row * PAD + cp2) = pk2(tf32c(b.x * f0), tf32c(b.y * f1));
        }
        // V fill: natural [64k][64d] -> tf32
        #pragma unroll
        for (int it = 0; it < 8; ++it) {
            int krow = fr + (it << 3);
            size_t vo = vbase + ((size_t)((c << 6) + krow) << 6) + cp2;
            float2 x = *(const float2*)(vr + vo);
            float2 y = *(const float2*)(vi + vo);
            *(u64*)(Vr + krow * PAD + cp2) = pk2(tf32c(x.x), tf32c(x.y));
            *(u64*)(Vi + krow * PAD + cp2) = pk2(tf32c(y.x), tf32c(y.y));
        }
        __syncthreads();

        #pragma unroll
        for (int kb = 0; kb < 8; ++kb) {
            const int kc = kb * 8 + tg;
            u32 aar[2][4], aai[2][4];
            #pragma unroll
            for (int mb = 0; mb < 2; ++mb) {
                int row = wm * 32 + mb * 16 + g;
                ldA(aar[mb], Ar, row, kc);
                ldA(aai[mb], Ai, row, kc);
            }
            #pragma unroll
            for (int nb = 0; nb < 4; ++nb) {
                int n0 = wn * 32 + nb * 8 + g;
                u32 bvr[2], bvi[2], bvn[2];
                bvr[0] = Vr[kc * PAD + n0];       bvr[1] = Vr[(kc + 4) * PAD + n0];
                bvi[0] = Vi[kc * PAD + n0];       bvi[1] = Vi[(kc + 4) * PAD + n0];
                bvn[0] = bvi[0] ^ NEGF;           bvn[1] = bvi[1] ^ NEGF;
                #pragma unroll
                for (int mb = 0; mb < 2; ++mb) {
                    mma_tf32(accR[mb][nb], aar[mb], bvr);
                    mma_tf32(accR[mb][nb], aai[mb], bvn);
                    mma_tf32(accI[mb][nb], aar[mb], bvi);
                    mma_tf32(accI[mb][nb], aai[mb], bvr);
                }
            }
        }
        __syncthreads();
    }

    // ---- epilogue: out[2][64][1024][64], imag at +4194304 ----
    #pragma unroll
    for (int mb = 0; mb < 2; ++mb)
        #pragma unroll
        for (int half = 0; half < 2; ++half) {
            int row = (qt << 7) + wm * 32 + mb * 16 + half * 8 + g;
            int d = wn * 32 + tg * 2;
            size_t ob = ((size_t)((bh << 10) + row) << 6) + d;
            #pragma unroll
            for (int nb = 0; nb < 4; ++nb) {
                *(float2*)(out + ob + nb * 8) =
                    make_float2(accR[mb][nb][half * 2], accR[mb][nb][half * 2 + 1]);
                *(float2*)(out + ob + nb * 8 + 4194304) =
                    make_float2(accI[mb][nb][half * 2], accI[mb][nb][half * 2 + 1]);
            }
        }
}

extern "C" void kernel_launch(void* const* d_in, const int* in_sizes, int n_in,
                              void* d_out, int out_size)
{
    (void)in_sizes; (void)n_in; (void)out_size;
    const float* qr = (const float*)d_in[0];
    const float* qi = (const float*)d_in[1];
    const float* kr = (const float*)d_in[2];
    const float* ki = (const float*)d_in[3];
    const float* vr = (const float*)d_in[4];
    const float* vi = (const float*)d_in[5];
    float* out = (float*)d_out;

    const int smem = (2 * QWORDS + 2 * KWORDS) * 4;   // 104448 B
    cudaFuncSetAttribute(qk_kernel, cudaFuncAttributeMaxDynamicSharedMemorySize, smem);
    cudaFuncSetAttribute(av_kernel, cudaFuncAttributeMaxDynamicSharedMemorySize, smem);

    qk_kernel<<<dim3(16, 8, 64), 256, smem>>>(qr, qi, kr, ki);
    minmax_kernel<<<256, 256>>>();
    av_kernel<<<dim3(8, 64), 256, smem>>>(vr, vi, out);
}